// round 2
// baseline (speedup 1.0000x reference)
#include <cuda_runtime.h>
#include <math.h>

#define BB 8
#define CC 256
#define NN 4096        // 64*64
#define WH 64
#define HEADS 4
#define KKC 16
#define VVC 64
#define MMK 23
#define PADK 11
#define OCH 144        // 64 q + 16 k + 64 v

// ---- scratch (static device globals; no allocation anywhere) ----
__device__ float g_Wf[OCH * CC];          // BN-folded weights
__device__ float g_bf[OCH];               // folded bias
__device__ float g_q [BB * 64 * NN];      // q after BN   (8.4 MB)
__device__ float g_kf[BB * 16 * NN];      // k, softmaxed in place
__device__ float g_v [BB * 64 * NN];      // v after BN
__device__ float g_lc[BB * 16 * 64];      // content lambda
__device__ float g_lp[(size_t)BB * 16 * 64 * NN]; // positional lambda (128 MiB)

// ============ K0: fold BN into weights ============
__global__ void fold_kernel(const float* __restrict__ Wq,
                            const float* __restrict__ qg, const float* __restrict__ qb,
                            const float* __restrict__ qm, const float* __restrict__ qv,
                            const float* __restrict__ Wk, const float* __restrict__ Wv,
                            const float* __restrict__ vg, const float* __restrict__ vb,
                            const float* __restrict__ vm, const float* __restrict__ vvar)
{
    int o = blockIdx.x;
    int c = threadIdx.x;
    float w, bias = 0.f;
    if (o < 64) {
        float s = qg[o] * rsqrtf(qv[o] + 1e-5f);
        w = Wq[o * CC + c] * s;
        bias = qb[o] - qm[o] * s;
    } else if (o < 80) {
        int oo = o - 64;
        w = Wk[oo * CC + c];
    } else {
        int oo = o - 80;
        float s = vg[oo] * rsqrtf(vvar[oo] + 1e-5f);
        w = Wv[oo * CC + c] * s;
        bias = vb[oo] - vm[oo] * s;
    }
    g_Wf[o * CC + c] = w;
    if (c == 0) g_bf[o] = bias;
}

// ============ K1: zero lambda_c (graph replays -> must re-zero) ============
__global__ void zero_lc_kernel()
{
    int i = blockIdx.x * 256 + threadIdx.x;
    if (i < BB * 16 * 64) g_lc[i] = 0.f;
}

// ============ K2: fused projection GEMM (144 x 4096, K=256) per batch ============
__global__ void __launch_bounds__(256) proj_kernel(const float* __restrict__ x)
{
    __shared__ float xs[32][132];
    __shared__ float ws[OCH][33];
    int b = blockIdx.y;
    int n0 = blockIdx.x * 128;
    int t = threadIdx.x;
    int tx = t & 15, ty = t >> 4;

    float acc[9][8];
#pragma unroll
    for (int r = 0; r < 9; r++)
#pragma unroll
        for (int j = 0; j < 8; j++) acc[r][j] = 0.f;

    for (int kc = 0; kc < CC; kc += 32) {
        for (int i = t; i < OCH * 32; i += 256) {
            int o = i >> 5, c = i & 31;
            ws[o][c] = g_Wf[o * CC + kc + c];
        }
        for (int i = t; i < 32 * 128; i += 256) {
            int c = i >> 7, n = i & 127;
            xs[c][n] = x[((size_t)b * CC + kc + c) * NN + n0 + n];
        }
        __syncthreads();
#pragma unroll 8
        for (int kk = 0; kk < 32; kk++) {
            float xv[8];
#pragma unroll
            for (int j = 0; j < 8; j++) xv[j] = xs[kk][tx * 8 + j];
#pragma unroll
            for (int r = 0; r < 9; r++) {
                float a = ws[ty + 16 * r][kk];
#pragma unroll
                for (int j = 0; j < 8; j++) acc[r][j] += a * xv[j];
            }
        }
        __syncthreads();
    }

#pragma unroll
    for (int r = 0; r < 9; r++) {
        int o = ty + 16 * r;
        float bias = g_bf[o];
        float* dst;
        if (o < 64)       dst = &g_q [((size_t)b * 64 + o)        * NN];
        else if (o < 80)  dst = &g_kf[((size_t)b * 16 + (o - 64)) * NN];
        else              dst = &g_v [((size_t)b * 64 + (o - 80)) * NN];
#pragma unroll
        for (int j = 0; j < 8; j++) dst[n0 + tx * 8 + j] = acc[r][j] + bias;
    }
}

// ============ K3: softmax over n for each (b,k) row ============
__global__ void softmax_kernel()
{
    int row = blockIdx.x;                 // b*16 + k
    float* p = &g_kf[(size_t)row * NN];
    int t = threadIdx.x;
    __shared__ float red[256];

    float vals[16];
    float m = -1e30f;
#pragma unroll
    for (int i = 0; i < 16; i++) {
        vals[i] = p[t + 256 * i];
        m = fmaxf(m, vals[i]);
    }
    red[t] = m; __syncthreads();
    for (int s = 128; s > 0; s >>= 1) {
        if (t < s) red[t] = fmaxf(red[t], red[t + s]);
        __syncthreads();
    }
    m = red[0]; __syncthreads();

    float sum = 0.f;
#pragma unroll
    for (int i = 0; i < 16; i++) {
        vals[i] = __expf(vals[i] - m);
        sum += vals[i];
    }
    red[t] = sum; __syncthreads();
    for (int s = 128; s > 0; s >>= 1) {
        if (t < s) red[t] += red[t + s];
        __syncthreads();
    }
    float inv = 1.f / red[0];
#pragma unroll
    for (int i = 0; i < 16; i++) p[t + 256 * i] = vals[i] * inv;
}

// ============ K4: lambda_c[b,k,v] = sum_n kf[b,k,n]*v[b,v,n] ============
__global__ void __launch_bounds__(256) lambdac_kernel()
{
    __shared__ float kfs[16][128];
    __shared__ float vs[64][128];
    int b = blockIdx.y;
    int n0 = blockIdx.x * 128;
    int t = threadIdx.x;

    for (int i = t; i < 16 * 128; i += 256) {
        int k = i >> 7, n = i & 127;
        kfs[k][n] = g_kf[((size_t)b * 16 + k) * NN + n0 + n];
    }
    for (int i = t; i < 64 * 128; i += 256) {
        int v = i >> 7, n = i & 127;
        vs[v][n] = g_v[((size_t)b * 64 + v) * NN + n0 + n];
    }
    __syncthreads();

#pragma unroll
    for (int pq = 0; pq < 4; pq++) {
        int pid = t + 256 * pq;           // 0..1023
        int k = pid >> 6, v = pid & 63;
        float a = 0.f;
#pragma unroll 8
        for (int nn = 0; nn < 128; nn++) a += kfs[k][nn] * vs[v][nn];
        atomicAdd(&g_lc[(size_t)b * 1024 + pid], a);
    }
}

// ============ K5: positional lambda — direct 23x23 conv, 16 filters ============
// grid (64 v, 8 b), 256 threads; each thread: 1 row x 16-px strip, all 16 k.
__global__ void __launch_bounds__(256) conv_kernel(const float* __restrict__ emb)
{
    __shared__ float img[86 * 87];        // padded image, row stride 87 (odd)
    __shared__ float embs[4 * 529];       // 4 filters at a time
    int v = blockIdx.x, b = blockIdx.y;
    int t = threadIdx.x;

    for (int i = t; i < 86 * 87; i += 256) img[i] = 0.f;
    __syncthreads();
    const float* vp = &g_v[((size_t)b * 64 + v) * NN];
    for (int i = t; i < NN; i += 256) {
        int r = i >> 6, c = i & 63;
        img[(r + PADK) * 87 + c + PADK] = vp[i];
    }

    int row = t >> 2, strip = t & 3, col0 = strip * 16;

#pragma unroll 1
    for (int kc = 0; kc < 4; kc++) {
        __syncthreads();                  // img ready / previous compute done
        for (int i = t; i < 4 * 529; i += 256) embs[i] = emb[kc * 4 * 529 + i];
        __syncthreads();

#pragma unroll 1
        for (int kk = 0; kk < 4; kk++) {
            float acc[16];
#pragma unroll
            for (int p = 0; p < 16; p++) acc[p] = 0.f;

#pragma unroll 1
            for (int di = 0; di < MMK; di++) {
                float win[38];
                const float* irow = &img[(row + di) * 87 + col0];
#pragma unroll
                for (int j = 0; j < 38; j++) win[j] = irow[j];
                const float* wr = &embs[kk * 529 + di * MMK];
#pragma unroll
                for (int dj = 0; dj < MMK; dj++) {
                    float w = wr[dj];
#pragma unroll
                    for (int p = 0; p < 16; p++) acc[p] += w * win[dj + p];
                }
            }
            float* dst = &g_lp[((((size_t)b * 16) + kc * 4 + kk) * 64 + v) * NN
                               + row * WH + col0];
#pragma unroll
            for (int p = 0; p < 16; p += 4) {
                float4 o4 = make_float4(acc[p], acc[p + 1], acc[p + 2], acc[p + 3]);
                *reinterpret_cast<float4*>(dst + p) = o4;
            }
        }
    }
}

// ============ K6: out[b, h*64+v, n] = sum_k q[b,h,k,n]*(lc[k,v]+lp[b,k,v,n]) ====
__global__ void __launch_bounds__(256) final_kernel(float* __restrict__ out)
{
    __shared__ float lcs[16 * 64];
    int b = blockIdx.y;
    int n = blockIdx.x * 256 + threadIdx.x;

    for (int i = threadIdx.x; i < 1024; i += 256) lcs[i] = g_lc[(size_t)b * 1024 + i];
    __syncthreads();

    float qv[64];
#pragma unroll
    for (int o = 0; o < 64; o++) qv[o] = g_q[((size_t)b * 64 + o) * NN + n];

#pragma unroll 1
    for (int v = 0; v < 64; v++) {
        float a0 = 0.f, a1 = 0.f, a2 = 0.f, a3 = 0.f;
#pragma unroll
        for (int k = 0; k < 16; k++) {
            float lam = lcs[k * 64 + v]
                      + g_lp[(((size_t)b * 16 + k) * 64 + v) * NN + n];
            a0 += qv[k]      * lam;
            a1 += qv[16 + k] * lam;
            a2 += qv[32 + k] * lam;
            a3 += qv[48 + k] * lam;
        }
        out[((size_t)b * 256 + 0 * 64 + v) * NN + n] = a0;
        out[((size_t)b * 256 + 1 * 64 + v) * NN + n] = a1;
        out[((size_t)b * 256 + 2 * 64 + v) * NN + n] = a2;
        out[((size_t)b * 256 + 3 * 64 + v) * NN + n] = a3;
    }
}

// ============ launcher ============
extern "C" void kernel_launch(void* const* d_in, const int* in_sizes, int n_in,
                              void* d_out, int out_size)
{
    const float* x   = (const float*)d_in[0];
    const float* Wq  = (const float*)d_in[1];
    const float* qg  = (const float*)d_in[2];
    const float* qb  = (const float*)d_in[3];
    const float* qm  = (const float*)d_in[4];
    const float* qv  = (const float*)d_in[5];
    const float* Wk  = (const float*)d_in[6];
    const float* Wv  = (const float*)d_in[7];
    const float* vg  = (const float*)d_in[8];
    const float* vb  = (const float*)d_in[9];
    const float* vm  = (const float*)d_in[10];
    const float* vvr = (const float*)d_in[11];
    const float* emb = (const float*)d_in[12];
    float* out = (float*)d_out;

    fold_kernel<<<OCH, 256>>>(Wq, qg, qb, qm, qv, Wk, Wv, vg, vb, vm, vvr);
    zero_lc_kernel<<<(BB * 16 * 64 + 255) / 256, 256>>>();
    proj_kernel<<<dim3(32, BB), 256>>>(x);
    conv_kernel<<<dim3(64, BB), 256>>>(emb);
    softmax_kernel<<<BB * 16, 256>>>();
    lambdac_kernel<<<dim3(32, BB), 256>>>();
    final_kernel<<<dim3(16, BB), 256>>>(out);
}

// round 4
// speedup vs baseline: 2.0807x; 2.0807x over previous
#include <cuda_runtime.h>
#include <math.h>

#define BB 8
#define CC 256
#define NN 4096        // 64*64
#define WH 64
#define HEADS 4
#define KKC 16
#define VVC 64
#define MMK 23
#define PADK 11
#define OCH 144        // 64 q + 16 k + 64 v

// ---- scratch (static device globals; no allocation anywhere) ----
__device__ float g_Wf[OCH * CC];          // BN-folded weights
__device__ float g_bf[OCH];               // folded bias
__device__ float g_q [BB * 64 * NN];      // q after BN   (8.4 MB)
__device__ float g_kf[BB * 16 * NN];      // k, softmaxed in place
__device__ float g_v [BB * 64 * NN];      // v after BN
__device__ float g_lc[BB * 16 * 64];      // content lambda

// ============ K0: fold BN into weights ============
__global__ void fold_kernel(const float* __restrict__ Wq,
                            const float* __restrict__ qg, const float* __restrict__ qb,
                            const float* __restrict__ qm, const float* __restrict__ qv,
                            const float* __restrict__ Wk, const float* __restrict__ Wv,
                            const float* __restrict__ vg, const float* __restrict__ vb,
                            const float* __restrict__ vm, const float* __restrict__ vvar)
{
    int o = blockIdx.x;
    int c = threadIdx.x;
    float w, bias = 0.f;
    if (o < 64) {
        float s = qg[o] * rsqrtf(qv[o] + 1e-5f);
        w = Wq[o * CC + c] * s;
        bias = qb[o] - qm[o] * s;
    } else if (o < 80) {
        int oo = o - 64;
        w = Wk[oo * CC + c];
    } else {
        int oo = o - 80;
        float s = vg[oo] * rsqrtf(vvar[oo] + 1e-5f);
        w = Wv[oo * CC + c] * s;
        bias = vb[oo] - vm[oo] * s;
    }
    g_Wf[o * CC + c] = w;
    if (c == 0) g_bf[o] = bias;
}

// ============ K1: zero lambda_c (graph replays -> must re-zero) ============
__global__ void zero_lc_kernel()
{
    int i = blockIdx.x * 256 + threadIdx.x;
    if (i < BB * 16 * 64) g_lc[i] = 0.f;
}

// ============ K2: fused projection GEMM (144 x 4096, K=256) per batch ============
__global__ void __launch_bounds__(256) proj_kernel(const float* __restrict__ x)
{
    __shared__ float xs[32][132];
    __shared__ float ws[OCH][33];
    int b = blockIdx.y;
    int n0 = blockIdx.x * 128;
    int t = threadIdx.x;
    int tx = t & 15, ty = t >> 4;

    float acc[9][8];
#pragma unroll
    for (int r = 0; r < 9; r++)
#pragma unroll
        for (int j = 0; j < 8; j++) acc[r][j] = 0.f;

    for (int kc = 0; kc < CC; kc += 32) {
        for (int i = t; i < OCH * 32; i += 256) {
            int o = i >> 5, c = i & 31;
            ws[o][c] = g_Wf[o * CC + kc + c];
        }
        for (int i = t; i < 32 * 128; i += 256) {
            int c = i >> 7, n = i & 127;
            xs[c][n] = x[((size_t)b * CC + kc + c) * NN + n0 + n];
        }
        __syncthreads();
#pragma unroll 8
        for (int kk = 0; kk < 32; kk++) {
            float xv[8];
#pragma unroll
            for (int j = 0; j < 8; j++) xv[j] = xs[kk][tx * 8 + j];
#pragma unroll
            for (int r = 0; r < 9; r++) {
                float a = ws[ty + 16 * r][kk];
#pragma unroll
                for (int j = 0; j < 8; j++) acc[r][j] += a * xv[j];
            }
        }
        __syncthreads();
    }

#pragma unroll
    for (int r = 0; r < 9; r++) {
        int o = ty + 16 * r;
        float bias = g_bf[o];
        float* dst;
        if (o < 64)       dst = &g_q [((size_t)b * 64 + o)        * NN];
        else if (o < 80)  dst = &g_kf[((size_t)b * 16 + (o - 64)) * NN];
        else              dst = &g_v [((size_t)b * 64 + (o - 80)) * NN];
#pragma unroll
        for (int j = 0; j < 8; j++) dst[n0 + tx * 8 + j] = acc[r][j] + bias;
    }
}

// ============ K3: softmax over n for each (b,k) row ============
__global__ void softmax_kernel()
{
    int row = blockIdx.x;                 // b*16 + k
    float* p = &g_kf[(size_t)row * NN];
    int t = threadIdx.x;
    __shared__ float red[256];

    float vals[16];
    float m = -1e30f;
#pragma unroll
    for (int i = 0; i < 16; i++) {
        vals[i] = p[t + 256 * i];
        m = fmaxf(m, vals[i]);
    }
    red[t] = m; __syncthreads();
    for (int s = 128; s > 0; s >>= 1) {
        if (t < s) red[t] = fmaxf(red[t], red[t + s]);
        __syncthreads();
    }
    m = red[0]; __syncthreads();

    float sum = 0.f;
#pragma unroll
    for (int i = 0; i < 16; i++) {
        vals[i] = __expf(vals[i] - m);
        sum += vals[i];
    }
    red[t] = sum; __syncthreads();
    for (int s = 128; s > 0; s >>= 1) {
        if (t < s) red[t] += red[t + s];
        __syncthreads();
    }
    float inv = 1.f / red[0];
#pragma unroll
    for (int i = 0; i < 16; i++) p[t + 256 * i] = vals[i] * inv;
}

// ============ K4: lambda_c[b,k,v] = sum_n kf[b,k,n]*v[b,v,n] ============
__global__ void __launch_bounds__(256) lambdac_kernel()
{
    __shared__ float kfs[16][128];
    __shared__ float vs[64][128];
    int b = blockIdx.y;
    int n0 = blockIdx.x * 128;
    int t = threadIdx.x;

    for (int i = t; i < 16 * 128; i += 256) {
        int k = i >> 7, n = i & 127;
        kfs[k][n] = g_kf[((size_t)b * 16 + k) * NN + n0 + n];
    }
    for (int i = t; i < 64 * 128; i += 256) {
        int v = i >> 7, n = i & 127;
        vs[v][n] = g_v[((size_t)b * 64 + v) * NN + n0 + n];
    }
    __syncthreads();

#pragma unroll
    for (int pq = 0; pq < 4; pq++) {
        int pid = t + 256 * pq;           // 0..1023
        int k = pid >> 6, v = pid & 63;
        float a = 0.f;
#pragma unroll 8
        for (int nn = 0; nn < 128; nn++) a += kfs[k][nn] * vs[v][nn];
        atomicAdd(&g_lc[(size_t)b * 1024 + pid], a);
    }
}

// ============ K5: fused positional lambda + output ============
// out[b, h*64+v, (r,c)] = sum_k q[h,k,(r,c)] * lc[k,v]
//                       + sum_{di,dj} s[h,(di,dj),(r,c)] * v[v, r+di-11, c+dj-11]
// where s[h,(di,dj),(r,c)] = sum_k q[h,k,(r,c)] * emb[k,di,dj]
//
// grid (64 rows, 8 b), 512 threads. Each thread owns (4h x 2v x 4c) outputs.
#define FUSED_SMEM_BYTES 100416

__global__ void __launch_bounds__(512, 1) fused_kernel(const float* __restrict__ emb,
                                                       float* __restrict__ out)
{
    extern __shared__ float sm[];
    float* q_s   = sm;            // [64][64]
    float* lc_s  = sm + 4096;     // [16][64]
    float* emb_s = sm + 5120;     // [16][529]
    float* s_s   = sm + 13584;    // [4][23][64]
    float* vr_s  = sm + 19472;    // [64][88]

    const int r = blockIdx.x, b = blockIdx.y;
    const int t = threadIdx.x;
    const int strip = t & 15;       // c-strip 0..15
    const int vpair = t >> 4;       // 0..31
    const int c0 = strip * 4;
    const int v0 = vpair * 2;

    // ---- persistent tiles ----
    for (int i = t; i < 4096; i += 512) {
        int ch = i >> 6, c = i & 63;
        q_s[i] = g_q[((size_t)b * 64 + ch) * NN + r * WH + c];
    }
    for (int i = t; i < 1024; i += 512) lc_s[i] = g_lc[b * 1024 + i];
    for (int i = t; i < 16 * 529; i += 512) emb_s[i] = emb[i];
    for (int i = t; i < 64 * 88; i += 512) vr_s[i] = 0.f;  // halo stays zero
    __syncthreads();

    // ---- init acc with content lambda term ----
    float acc[4][2][4];
#pragma unroll
    for (int h = 0; h < 4; h++)
#pragma unroll
        for (int v = 0; v < 2; v++)
#pragma unroll
            for (int c = 0; c < 4; c++) acc[h][v][c] = 0.f;

    const float4* q4 = (const float4*)q_s;      // [64][16] float4
#pragma unroll
    for (int k = 0; k < 16; k++) {
        float l0 = lc_s[k * 64 + v0];
        float l1 = lc_s[k * 64 + v0 + 1];
#pragma unroll
        for (int h = 0; h < 4; h++) {
            float4 qv = q4[(h * 16 + k) * 16 + strip];
            acc[h][0][0] += qv.x * l0; acc[h][0][1] += qv.y * l0;
            acc[h][0][2] += qv.z * l0; acc[h][0][3] += qv.w * l0;
            acc[h][1][0] += qv.x * l1; acc[h][1][1] += qv.y * l1;
            acc[h][1][2] += qv.z * l1; acc[h][1][3] += qv.w * l1;
        }
    }

    // ---- positional term: loop over filter rows di ----
    const int di_lo = (r < PADK) ? (PADK - r) : 0;
    const int di_hi = (r > 52) ? (74 - r) : 22;   // r+di-11 <= 63

    const float* vbase = &g_v[(size_t)b * 64 * NN];
    float4* s4 = (float4*)s_s;                    // [4*23][16] float4

#pragma unroll 1
    for (int di = di_lo; di <= di_hi; di++) {
        const int rr = r + di - PADK;
        __syncthreads();   // previous apply done before overwriting vr_s/s_s

        // load v image row rr for all 64 channels
        for (int i = t; i < 4096; i += 512) {
            int v = i >> 6, c = i & 63;
            vr_s[v * 88 + PADK + c] = vbase[(size_t)v * NN + rr * WH + c];
        }

        // compute s[h][dj][c] = sum_k q[h,k,c] * emb[k,di,dj] (quads of c)
        for (int i = t; i < 1472; i += 512) {
            int h = i / 368, rem = i % 368;
            int dj = rem >> 4, cq = rem & 15;
            float4 sv = make_float4(0.f, 0.f, 0.f, 0.f);
            const float* ep = &emb_s[di * MMK + dj];   // FIXED: no h term; k stride 529
#pragma unroll
            for (int k = 0; k < 16; k++) {
                float w = ep[k * 529];
                float4 qv = q4[(h * 16 + k) * 16 + cq];
                sv.x += w * qv.x; sv.y += w * qv.y;
                sv.z += w * qv.z; sv.w += w * qv.w;
            }
            s4[(h * 23 + dj) * 16 + cq] = sv;
        }
        __syncthreads();

        // register sliding window of v for this thread's 2 channels
        float vw[2][28];
#pragma unroll
        for (int v = 0; v < 2; v++)
#pragma unroll
            for (int j = 0; j < 7; j++) {
                float4 x4 = *(const float4*)&vr_s[(v0 + v) * 88 + c0 + j * 4];
                vw[v][j * 4 + 0] = x4.x; vw[v][j * 4 + 1] = x4.y;
                vw[v][j * 4 + 2] = x4.z; vw[v][j * 4 + 3] = x4.w;
            }

        // apply 23 taps
#pragma unroll
        for (int dj = 0; dj < MMK; dj++) {
            float4 sh[4];
#pragma unroll
            for (int h = 0; h < 4; h++) sh[h] = s4[(h * 23 + dj) * 16 + strip];
#pragma unroll
            for (int h = 0; h < 4; h++) {
#pragma unroll
                for (int v = 0; v < 2; v++) {
                    acc[h][v][0] += sh[h].x * vw[v][dj + 0];
                    acc[h][v][1] += sh[h].y * vw[v][dj + 1];
                    acc[h][v][2] += sh[h].z * vw[v][dj + 2];
                    acc[h][v][3] += sh[h].w * vw[v][dj + 3];
                }
            }
        }
    }

    // ---- write output ----
#pragma unroll
    for (int h = 0; h < 4; h++)
#pragma unroll
        for (int v = 0; v < 2; v++) {
            float4 o4 = make_float4(acc[h][v][0], acc[h][v][1],
                                    acc[h][v][2], acc[h][v][3]);
            *(float4*)&out[((size_t)b * 256 + h * 64 + v0 + v) * NN + r * WH + c0] = o4;
        }
}

// ============ launcher ============
extern "C" void kernel_launch(void* const* d_in, const int* in_sizes, int n_in,
                              void* d_out, int out_size)
{
    const float* x   = (const float*)d_in[0];
    const float* Wq  = (const float*)d_in[1];
    const float* qg  = (const float*)d_in[2];
    const float* qb  = (const float*)d_in[3];
    const float* qm  = (const float*)d_in[4];
    const float* qv  = (const float*)d_in[5];
    const float* Wk  = (const float*)d_in[6];
    const float* Wv  = (const float*)d_in[7];
    const float* vg  = (const float*)d_in[8];
    const float* vb  = (const float*)d_in[9];
    const float* vm  = (const float*)d_in[10];
    const float* vvr = (const float*)d_in[11];
    const float* emb = (const float*)d_in[12];
    float* out = (float*)d_out;

    cudaFuncSetAttribute(fused_kernel,
                         cudaFuncAttributeMaxDynamicSharedMemorySize,
                         FUSED_SMEM_BYTES);

    fold_kernel<<<OCH, 256>>>(Wq, qg, qb, qm, qv, Wk, Wv, vg, vb, vm, vvr);
    zero_lc_kernel<<<(BB * 16 * 64 + 255) / 256, 256>>>();
    proj_kernel<<<dim3(32, BB), 256>>>(x);
    softmax_kernel<<<BB * 16, 256>>>();
    lambdac_kernel<<<dim3(32, BB), 256>>>();
    fused_kernel<<<dim3(WH, BB), 512, FUSED_SMEM_BYTES>>>(emb, out);
}

// round 5
// speedup vs baseline: 2.6916x; 1.2936x over previous
#include <cuda_runtime.h>
#include <math.h>

#define BB 8
#define CC 256
#define NN 4096        // 64*64
#define WH 64
#define HEADS 4
#define KKC 16
#define VVC 64
#define MMK 23
#define PADK 11
#define OCH 144        // 64 q + 16 k + 64 v

// ---- scratch (static device globals; no allocation anywhere) ----
__device__ float g_Wf[OCH * CC];          // BN-folded weights
__device__ float g_bf[OCH];               // folded bias
__device__ float g_q [BB * 64 * NN];      // q after BN
__device__ float g_kf[BB * 16 * NN];      // k, softmaxed in place
__device__ float g_v [BB * 64 * NN];      // v after BN
__device__ float g_lc[BB * 16 * 64];      // content lambda

// ============ K0: fold BN into weights ============
__global__ void fold_kernel(const float* __restrict__ Wq,
                            const float* __restrict__ qg, const float* __restrict__ qb,
                            const float* __restrict__ qm, const float* __restrict__ qv,
                            const float* __restrict__ Wk, const float* __restrict__ Wv,
                            const float* __restrict__ vg, const float* __restrict__ vb,
                            const float* __restrict__ vm, const float* __restrict__ vvar)
{
    int o = blockIdx.x;
    int c = threadIdx.x;
    float w, bias = 0.f;
    if (o < 64) {
        float s = qg[o] * rsqrtf(qv[o] + 1e-5f);
        w = Wq[o * CC + c] * s;
        bias = qb[o] - qm[o] * s;
    } else if (o < 80) {
        int oo = o - 64;
        w = Wk[oo * CC + c];
    } else {
        int oo = o - 80;
        float s = vg[oo] * rsqrtf(vvar[oo] + 1e-5f);
        w = Wv[oo * CC + c] * s;
        bias = vb[oo] - vm[oo] * s;
    }
    g_Wf[o * CC + c] = w;
    if (c == 0) g_bf[o] = bias;
}

// ============ K1: zero lambda_c (graph replays -> must re-zero) ============
__global__ void zero_lc_kernel()
{
    int i = blockIdx.x * 256 + threadIdx.x;
    if (i < BB * 16 * 64) g_lc[i] = 0.f;
}

// ============ K2: fused projection GEMM (144 x 4096, K=256) per batch ============
__global__ void __launch_bounds__(256) proj_kernel(const float* __restrict__ x)
{
    __shared__ float xs[32][132];
    __shared__ float ws[OCH][33];
    int b = blockIdx.y;
    int n0 = blockIdx.x * 128;
    int t = threadIdx.x;
    int tx = t & 15, ty = t >> 4;

    float acc[9][8];
#pragma unroll
    for (int r = 0; r < 9; r++)
#pragma unroll
        for (int j = 0; j < 8; j++) acc[r][j] = 0.f;

    for (int kc = 0; kc < CC; kc += 32) {
        for (int i = t; i < OCH * 32; i += 256) {
            int o = i >> 5, c = i & 31;
            ws[o][c] = g_Wf[o * CC + kc + c];
        }
        for (int i = t; i < 32 * 128; i += 256) {
            int c = i >> 7, n = i & 127;
            xs[c][n] = x[((size_t)b * CC + kc + c) * NN + n0 + n];
        }
        __syncthreads();
#pragma unroll 8
        for (int kk = 0; kk < 32; kk++) {
            float xv[8];
#pragma unroll
            for (int j = 0; j < 8; j++) xv[j] = xs[kk][tx * 8 + j];
#pragma unroll
            for (int r = 0; r < 9; r++) {
                float a = ws[ty + 16 * r][kk];
#pragma unroll
                for (int j = 0; j < 8; j++) acc[r][j] += a * xv[j];
            }
        }
        __syncthreads();
    }

#pragma unroll
    for (int r = 0; r < 9; r++) {
        int o = ty + 16 * r;
        float bias = g_bf[o];
        float* dst;
        if (o < 64)       dst = &g_q [((size_t)b * 64 + o)        * NN];
        else if (o < 80)  dst = &g_kf[((size_t)b * 16 + (o - 64)) * NN];
        else              dst = &g_v [((size_t)b * 64 + (o - 80)) * NN];
#pragma unroll
        for (int j = 0; j < 8; j++) dst[n0 + tx * 8 + j] = acc[r][j] + bias;
    }
}

// ============ K3: softmax over n for each (b,k) row ============
__global__ void softmax_kernel()
{
    int row = blockIdx.x;                 // b*16 + k
    float* p = &g_kf[(size_t)row * NN];
    int t = threadIdx.x;
    __shared__ float red[256];

    float vals[16];
    float m = -1e30f;
#pragma unroll
    for (int i = 0; i < 16; i++) {
        vals[i] = p[t + 256 * i];
        m = fmaxf(m, vals[i]);
    }
    red[t] = m; __syncthreads();
    for (int s = 128; s > 0; s >>= 1) {
        if (t < s) red[t] = fmaxf(red[t], red[t + s]);
        __syncthreads();
    }
    m = red[0]; __syncthreads();

    float sum = 0.f;
#pragma unroll
    for (int i = 0; i < 16; i++) {
        vals[i] = __expf(vals[i] - m);
        sum += vals[i];
    }
    red[t] = sum; __syncthreads();
    for (int s = 128; s > 0; s >>= 1) {
        if (t < s) red[t] += red[t + s];
        __syncthreads();
    }
    float inv = 1.f / red[0];
#pragma unroll
    for (int i = 0; i < 16; i++) p[t + 256 * i] = vals[i] * inv;
}

// ============ K4: lambda_c[b,k,v] = sum_n kf[b,k,n]*v[b,v,n] ============
__global__ void __launch_bounds__(256) lambdac_kernel()
{
    __shared__ float kfs[16][128];
    __shared__ float vs[64][128];
    int b = blockIdx.y;
    int n0 = blockIdx.x * 128;
    int t = threadIdx.x;

    for (int i = t; i < 16 * 128; i += 256) {
        int k = i >> 7, n = i & 127;
        kfs[k][n] = g_kf[((size_t)b * 16 + k) * NN + n0 + n];
    }
    for (int i = t; i < 64 * 128; i += 256) {
        int v = i >> 7, n = i & 127;
        vs[v][n] = g_v[((size_t)b * 64 + v) * NN + n0 + n];
    }
    __syncthreads();

#pragma unroll
    for (int pq = 0; pq < 4; pq++) {
        int pid = t + 256 * pq;           // 0..1023
        int k = pid >> 6, v = pid & 63;
        float a = 0.f;
#pragma unroll 8
        for (int nn = 0; nn < 128; nn++) a += kfs[k][nn] * vs[v][nn];
        atomicAdd(&g_lc[(size_t)b * 1024 + pid], a);
    }
}

// ============ K5: fused positional lambda + output (v2, 256 thr, 4h x 4v x 4c) ====
// out[b, h*64+v, (r,c)] = sum_k q[h,k,(r,c)] * lc[k,v]
//                       + sum_{di,dj} s[h,(di,dj),(r,c)] * v[v, r+di-11, c+dj-11]
// where s[h,(di,dj),(r,c)] = sum_k q[h,k,(r,c)] * emb[k,di,dj]
#define FUSED_SMEM_BYTES 100416

__global__ void __launch_bounds__(256) fused_kernel(const float* __restrict__ emb,
                                                    float* __restrict__ out)
{
    extern __shared__ float sm[];
    float* q_s   = sm;            // [64][64]   (ch = h*16+k, col)
    float* lc_s  = sm + 4096;     // [16][64]
    float* emb_s = sm + 5120;     // [16][529]
    float* s_s   = sm + 13584;    // [4h][23dj][64c]
    float* vr_s  = sm + 19472;    // [64v][88]

    const int r = blockIdx.x, b = blockIdx.y;
    const int t = threadIdx.x;
    const int strip  = t & 15;      // c-strip 0..15
    const int vgroup = t >> 4;      // 0..15
    const int c0 = strip * 4;
    const int v0 = vgroup * 4;

    // s-compute assignment: fixed (h, cq), a range of dj
    const int cq  = t & 15;
    const int hh  = (t >> 4) & 3;
    const int djb = (t >> 6) * 6;   // 0,6,12,18

    // ---- persistent tiles ----
    for (int i = t; i < 4096; i += 256) {
        int ch = i >> 6, c = i & 63;
        q_s[i] = g_q[((size_t)b * 64 + ch) * NN + r * WH + c];
    }
    for (int i = t; i < 1024; i += 256) lc_s[i] = g_lc[b * 1024 + i];
    for (int i = t; i < 16 * 529; i += 256) emb_s[i] = emb[i];
    for (int i = t; i < 64 * 88; i += 256) vr_s[i] = 0.f;  // halo stays zero
    __syncthreads();

    // ---- init acc with content lambda term ----
    float acc[4][4][4];
#pragma unroll
    for (int h = 0; h < 4; h++)
#pragma unroll
        for (int v = 0; v < 4; v++)
#pragma unroll
            for (int c = 0; c < 4; c++) acc[h][v][c] = 0.f;

    const float4* q4 = (const float4*)q_s;      // [64 ch][16] float4
#pragma unroll
    for (int k = 0; k < 16; k++) {
        float lv[4];
#pragma unroll
        for (int v = 0; v < 4; v++) lv[v] = lc_s[k * 64 + v0 + v];
#pragma unroll
        for (int h = 0; h < 4; h++) {
            float4 qv = q4[(h * 16 + k) * 16 + strip];
#pragma unroll
            for (int v = 0; v < 4; v++) {
                acc[h][v][0] += qv.x * lv[v]; acc[h][v][1] += qv.y * lv[v];
                acc[h][v][2] += qv.z * lv[v]; acc[h][v][3] += qv.w * lv[v];
            }
        }
    }

    // ---- positional term: loop over filter rows di ----
    const int di_lo = (r < PADK) ? (PADK - r) : 0;
    const int di_hi = (r > 52) ? (74 - r) : 22;   // r+di-11 <= 63

    const float* vbase = &g_v[(size_t)b * 64 * NN];
    float4* s4 = (float4*)s_s;                    // [4*23][16] float4

#pragma unroll 1
    for (int di = di_lo; di <= di_hi; di++) {
        const int rr = r + di - PADK;
        __syncthreads();   // previous apply done before overwriting vr_s/s_s

        // load v image row rr for all 64 channels
        for (int i = t; i < 4096; i += 256) {
            int v = i >> 6, c = i & 63;
            vr_s[v * 88 + PADK + c] = vbase[(size_t)v * NN + rr * WH + c];
        }

        // compute s: this thread covers (hh, cq) for dj in [djb, djb+5]
        {
            float4 qreg[16];
#pragma unroll
            for (int k = 0; k < 16; k++) qreg[k] = q4[(hh * 16 + k) * 16 + cq];
            const float* ebase = &emb_s[di * MMK];
#pragma unroll
            for (int jj = 0; jj < 6; jj++) {
                int dj = djb + jj;
                if (dj < MMK) {
                    float4 sv = make_float4(0.f, 0.f, 0.f, 0.f);
#pragma unroll
                    for (int k = 0; k < 16; k++) {
                        float w = ebase[k * 529 + dj];   // full-warp broadcast
                        sv.x += w * qreg[k].x; sv.y += w * qreg[k].y;
                        sv.z += w * qreg[k].z; sv.w += w * qreg[k].w;
                    }
                    s4[(hh * 23 + dj) * 16 + cq] = sv;
                }
            }
        }
        __syncthreads();

        // apply 23 taps in two half-passes (window of 16 floats per v)
#pragma unroll
        for (int pass = 0; pass < 2; pass++) {
            const int base = pass * 12;
            const int ntap = pass ? 11 : 12;

            float vw[4][16];
#pragma unroll
            for (int v = 0; v < 4; v++)
#pragma unroll
                for (int j = 0; j < 4; j++) {
                    float4 x4 = *(const float4*)&vr_s[(v0 + v) * 88 + c0 + base + j * 4];
                    vw[v][j * 4 + 0] = x4.x; vw[v][j * 4 + 1] = x4.y;
                    vw[v][j * 4 + 2] = x4.z; vw[v][j * 4 + 3] = x4.w;
                }

#pragma unroll
            for (int djl = 0; djl < 12; djl++) {
                if (djl >= ntap) break;
                const int dj = base + djl;
                float4 sh[4];
#pragma unroll
                for (int h = 0; h < 4; h++) sh[h] = s4[(h * 23 + dj) * 16 + strip];
#pragma unroll
                for (int h = 0; h < 4; h++)
#pragma unroll
                    for (int v = 0; v < 4; v++) {
                        acc[h][v][0] += sh[h].x * vw[v][djl + 0];
                        acc[h][v][1] += sh[h].y * vw[v][djl + 1];
                        acc[h][v][2] += sh[h].z * vw[v][djl + 2];
                        acc[h][v][3] += sh[h].w * vw[v][djl + 3];
                    }
            }
        }
    }

    // ---- write output ----
#pragma unroll
    for (int h = 0; h < 4; h++)
#pragma unroll
        for (int v = 0; v < 4; v++) {
            float4 o4 = make_float4(acc[h][v][0], acc[h][v][1],
                                    acc[h][v][2], acc[h][v][3]);
            *(float4*)&out[((size_t)b * 256 + h * 64 + v0 + v) * NN + r * WH + c0] = o4;
        }
}

// ============ launcher ============
extern "C" void kernel_launch(void* const* d_in, const int* in_sizes, int n_in,
                              void* d_out, int out_size)
{
    const float* x   = (const float*)d_in[0];
    const float* Wq  = (const float*)d_in[1];
    const float* qg  = (const float*)d_in[2];
    const float* qb  = (const float*)d_in[3];
    const float* qm  = (const float*)d_in[4];
    const float* qv  = (const float*)d_in[5];
    const float* Wk  = (const float*)d_in[6];
    const float* Wv  = (const float*)d_in[7];
    const float* vg  = (const float*)d_in[8];
    const float* vb  = (const float*)d_in[9];
    const float* vm  = (const float*)d_in[10];
    const float* vvr = (const float*)d_in[11];
    const float* emb = (const float*)d_in[12];
    float* out = (float*)d_out;

    cudaFuncSetAttribute(fused_kernel,
                         cudaFuncAttributeMaxDynamicSharedMemorySize,
                         FUSED_SMEM_BYTES);

    fold_kernel<<<OCH, 256>>>(Wq, qg, qb, qm, qv, Wk, Wv, vg, vb, vm, vvr);
    zero_lc_kernel<<<(BB * 16 * 64 + 255) / 256, 256>>>();
    proj_kernel<<<dim3(32, BB), 256>>>(x);
    softmax_kernel<<<BB * 16, 256>>>();
    lambdac_kernel<<<dim3(32, BB), 256>>>();
    fused_kernel<<<dim3(WH, BB), 256, FUSED_SMEM_BYTES>>>(emb, out);
}